// round 17
// baseline (speedup 1.0000x reference)
#include <cuda_runtime.h>
#include <cstdint>

// DangoCutouts: 16 x (3,512,512) fp32 outputs from one (3,4096,4096) image.
// blockIdx.x = image slot (13, offy-sorted)  <- FAST dim (banded co-scheduling)
// blockIdx.y = row chunk                     <- SLOW dim
// 4 output rows per thread, TPB=256 (keeps >=6 CTAs/SM at ~42 regs).
// Lane-consecutive x; streaming stores; uint32 row offsets.

#define H 4096
#define W 4096
#define CUT 512
#define CH_STRIDE (4096u * 4096u)
#define PLANE (CUT * CUT)
#define N_INNER 12
#define TPB 256
#define RPT 4

struct Taps { int x0, x1; float wx; };

__device__ __forceinline__ Taps tap1d(int o, int size, float s, float sc, int i)
{
    float f = (float)o + (((float)i + 0.5f) * sc - 0.5f);
    f = fminf(fmaxf(f, (float)o), (float)o + s - 1.0f);
    Taps t;
    t.x0 = (int)floorf(f);
    t.x1 = min(t.x0 + 1, o + size - 1);
    t.wx = f - (float)t.x0;
    return t;
}

__global__ __launch_bounds__(TPB)
void dango_cutouts_kernel(const float* __restrict__ img,
                          const int*   __restrict__ sizes,
                          const int*   __restrict__ offy,
                          const int*   __restrict__ offx,
                          float*       __restrict__ out)
{
    const int p  = blockIdx.y * TPB + threadIdx.x;          // 0 .. 512*128-1
    const int g  = blockIdx.x;                               // 0 .. 12 (fast dim)
    const int xo = p & 511;                                  // lane-consecutive x
    const int yo = (p >> 9) << 2;                            // first of 4 rows

    // Per-block offy-sorted permutation: sperm[rank] = crop index.
    __shared__ int sperm[N_INNER];
    if (threadIdx.x < N_INNER) {
        const int cand = threadIdx.x;
        const int oyc  = __ldg(offy + cand);
        int rank = 0;
#pragma unroll
        for (int k = 0; k < N_INNER; ++k) {
            const int oyk = __ldg(offy + k);
            rank += (oyk < oyc) || (oyk == oyc && k < cand);
        }
        sperm[rank] = cand;
    }
    __syncthreads();

    int oy, ox, sz, j = -1;
    if (g == 0) { oy = 0; ox = 0; sz = 4096; }
    else {
        j  = sperm[g - 1];
        oy = __ldg(offy  + j);
        ox = __ldg(offx  + j);
        sz = __ldg(sizes + j);
    }

    const float s  = (float)sz;
    const float sc = s * (1.0f / 512.0f);   // exact pow2 scale

    const Taps tx = tap1d(ox, sz, s, sc, xo);

    uint32_t r0[RPT], r1[RPT];
    float    wy[RPT];
#pragma unroll
    for (int r = 0; r < RPT; ++r) {
        const Taps ty = tap1d(oy, sz, s, sc, yo + r);
        r0[r] = (uint32_t)ty.x0 * (uint32_t)W;
        r1[r] = (uint32_t)ty.x1 * (uint32_t)W;
        wy[r] = ty.wx;
    }

    float v[RPT][3];
#pragma unroll
    for (int c = 0; c < 3; ++c) {
        const float* base = img + (size_t)c * CH_STRIDE;
#pragma unroll
        for (int r = 0; r < RPT; ++r) {
            const float v00 = __ldg(base + r0[r] + tx.x0);
            const float v01 = __ldg(base + r0[r] + tx.x1);
            const float v10 = __ldg(base + r1[r] + tx.x0);
            const float v11 = __ldg(base + r1[r] + tx.x1);
            const float top = v00 + (v01 - v00) * tx.wx;
            const float bot = v10 + (v11 - v10) * tx.wx;
            v[r][c] = top + (bot - top) * wy[r];
        }
    }

    if (g == 0) {
#pragma unroll
        for (int r = 0; r < RPT; ++r) {
            const float gr = 0.2989f * v[r][0] + 0.587f * v[r][1] + 0.114f * v[r][2];
            const size_t row = (size_t)(yo + r) * CUT;
            const size_t pf  = row + xo;
            const size_t pr  = row + (511 - xo);
#pragma unroll
            for (int c = 0; c < 3; ++c) {
                const size_t cp = (size_t)c * PLANE;
                __stcs(out + 0 * PLANE + cp + pf, v[r][c]);   // img0 full
                __stcs(out + 3 * PLANE + cp + pf, gr);        // img1 gray
                __stcs(out + 6 * PLANE + cp + pr, v[r][c]);   // img2 flip
                __stcs(out + 9 * PLANE + cp + pr, gr);        // img3 gray-flip
            }
        }
    } else {
        if (j == 0) {   // crop 0 (original index) is grayed
#pragma unroll
            for (int r = 0; r < RPT; ++r) {
                const float gr = 0.2989f * v[r][0] + 0.587f * v[r][1] + 0.114f * v[r][2];
                v[r][0] = v[r][1] = v[r][2] = gr;
            }
        }
        const size_t obase = ((size_t)(j + 4) * 3) * PLANE + (size_t)yo * CUT + xo;
#pragma unroll
        for (int c = 0; c < 3; ++c) {
#pragma unroll
            for (int r = 0; r < RPT; ++r)
                __stcs(out + obase + (size_t)c * PLANE + (size_t)r * CUT, v[r][c]);
        }
    }
}

extern "C" void kernel_launch(void* const* d_in, const int* in_sizes, int n_in,
                              void* d_out, int out_size)
{
    const float* img   = (const float*)d_in[0];
    // d_in[1] = t (unused)
    const int*   sizes = (const int*)d_in[2];
    const int*   offy  = (const int*)d_in[3];
    const int*   offx  = (const int*)d_in[4];
    float*       out   = (float*)d_out;

    dim3 block(TPB, 1, 1);
    dim3 grid(13, (PLANE / RPT) / TPB, 1);   // image fast, chunk slow (banded)
    dango_cutouts_kernel<<<grid, block>>>(img, sizes, offy, offx, out);
}